// round 10
// baseline (speedup 1.0000x reference)
#include <cuda_runtime.h>
#include <math.h>

#define NG     320
#define NS1    (NG*NG)
#define NSA    (NSHOT*NS1)
#define NSHOT  2
#define NSRC   8
#define NREC   96
#define NT     160
#define NROUND (NT/2)
#define PML_W  20
#define NBLK   256          // 128 tiles x 2 shots
#define TPB    400
#define TILE_R 20
#define TILE_C 40
#define TCB    8
#define TRB    16
#define SSP    57           // stress frame stride; rows 36 (core+-8), cols 56
#define SVP    53           // velocity frame stride; rows 32 (core+-6), cols 52
#define IDHF   0.25f
#define DTF    4.0e-4f

// Double-buffered full state exchange (values + all 8 CPML fields)
__device__ float g_syy[2][NSHOT*NS1], g_sxy[2][NSHOT*NS1], g_sxx[2][NSHOT*NS1];
__device__ float g_vyf[2][NSHOT*NS1], g_vxf[2][NSHOT*NS1];
__device__ float g_ms1[2][NSHOT*NS1], g_ms2[2][NSHOT*NS1];   // msyyy, msxyx
__device__ float g_ms3[2][NSHOT*NS1], g_ms4[2][NSHOT*NS1];   // msxxx, msxyy
__device__ float g_mv1[2][NSHOT*NS1], g_mv2[2][NSHOT*NS1];   // mvyy, mvxx
__device__ float g_mv3[2][NSHOT*NS1], g_mv4[2][NSHOT*NS1];   // mvyx, mvxy
__device__ float g_recs[NT*NSHOT*NREC];

__device__ __align__(128) unsigned g_flag[NBLK*32];
__device__ __align__(128) unsigned g_count = 0;
__device__ __align__(128) volatile unsigned g_phase = 0;

__device__ __forceinline__ void gbar(unsigned target)
{
    __syncthreads();
    if (threadIdx.x == 0) {
        __threadfence();
        if (atomicAdd(&g_count, 1u) == NBLK - 1) {
            g_count = 0;
            __threadfence();
            g_phase = target;
        } else {
            while ((int)(g_phase - target) < 0) { }
        }
        __threadfence();
    }
    __syncthreads();
}

__device__ __forceinline__ unsigned ld_acq(const unsigned* p)
{
    unsigned v;
    asm volatile("ld.acquire.gpu.global.u32 %0, [%1];" : "=r"(v) : "l"(p) : "memory");
    return v;
}
__device__ __forceinline__ void red_add(unsigned* p)
{
    asm volatile("red.global.add.u32 [%0], %1;" :: "l"(p), "r"(1u) : "memory");
}

__device__ __forceinline__ float pml_b(int i)
{
    const double d0 = 3.0 * 1600.0 * log(1000.0) / (2.0 * PML_W * 4.0);
    double dd = 0.0;
    if (i < PML_W) {
        double a = (double)(PML_W - i) / PML_W;
        dd = d0 * a * a;
    } else if (i >= NG - PML_W) {
        double a = ((double)i - (NG - 1 - PML_W)) / PML_W;
        dd = d0 * a * a;
    }
    return (float)exp(-dd * 4.0e-4);
}

__device__ __forceinline__ int gw(int v) { return (v + NG) % NG; }

__device__ __forceinline__ void st2(float* __restrict__ p, int idx, float a, float b)
{
    *reinterpret_cast<float2*>(p + idx) = make_float2(a, b);
}

// ring pair enumerations (frame coords packed: (r+8)<<8 | (c+8), c even)
__device__ __forceinline__ int vring_rc(int k)
{
    int r, pc;
    if (k < 128) {            // annulus 1..2 (updated both steps)
        if (k < 44)       { r = -2 + k / 22;        pc = -1 + k % 22; }
        else if (k < 88)  { r = 20 + (k - 44) / 22; pc = -1 + (k - 44) % 22; }
        else if (k < 108) { r = k - 88;             pc = -1; }
        else              { r = k - 108;            pc = 20; }
    } else {                  // annulus 3..6 (step t only)
        int j = k - 128;
        if (j < 104)      { r = -6 + j / 26;         pc = -3 + j % 26; }
        else if (j < 208) { r = 22 + (j - 104) / 26; pc = -3 + (j - 104) % 26; }
        else if (j < 256) { int jj = j - 208; r = -2 + jj / 2; pc = -3 + jj % 2; }
        else              { int jj = j - 256; r = -2 + jj / 2; pc = 21 + jj % 2; }
    }
    return ((r + 8) << 8) | (2 * pc + 8);
}
__device__ __forceinline__ int sring_rc(int k)
{
    int r, pc;
    if (k < 96)       { r = -4 + k / 24;        pc = -2 + k % 24; }
    else if (k < 192) { r = 20 + (k - 96) / 24; pc = -2 + (k - 96) % 24; }
    else if (k < 232) { int kk = k - 192; r = kk / 2; pc = -2 + kk % 2; }
    else              { int kk = k - 232; r = kk / 2; pc = 20 + kk % 2; }
    return ((r + 8) << 8) | (2 * pc + 8);
}

__global__ __launch_bounds__(TPB, 2) void sim_kernel(
    const float* __restrict__ lamb,
    const float* __restrict__ mu,
    const float* __restrict__ buoy,
    const float* __restrict__ amps,
    const int*   __restrict__ sloc,
    const int*   __restrict__ rloc,
    float* __restrict__ out)
{
    __shared__ float s_syy[36*SSP], s_sxy[36*SSP], s_sxx[36*SSP];
    __shared__ float s_vy [32*SVP], s_vx [32*SVP];
    __shared__ float s_pml[NG];

    const int tid  = threadIdx.x;
    const int blk  = blockIdx.x;
    const int shot = blk & 1;
    const int tile = blk >> 1;
    const int by0 = (tile / TCB) * TILE_R;
    const int bx0 = (tile % TCB) * TILE_C;
    const int rr = tid / 20;
    const int pp = tid - rr * 20;
    const int cx = 2 * pp;
    const int y  = by0 + rr;
    const int x0 = bx0 + cx;
    const int base = shot * NS1;
    const int o = y * NG + x0;
    unsigned ph = g_phase;
    const unsigned F = g_flag[blk * 32];

    int nbid = 0;
    if (tid < 8) {
        const int dR[8] = {-1,-1,-1, 0, 0, 1, 1, 1};
        const int dC[8] = {-1, 0, 1,-1, 1,-1, 0, 1};
        int bR = tile / TCB, bC = tile % TCB;
        int nR = (bR + dR[tid] + TRB) % TRB;
        int nC = (bC + dC[tid] + TCB) % TCB;
        nbid = ((nR * TCB + nC) << 1) | shot;
    }

    // pml table
    if (tid < NG) s_pml[tid] = pml_b(tid);

    // ---- core constants ----
    const float2 bv2  = *reinterpret_cast<const float2*>(buoy + o);
    const float2 lam2 = *reinterpret_cast<const float2*>(lamb + o);
    const float2 mu2  = *reinterpret_cast<const float2*>(mu + o);
    const bool ybord = (y < 2 || y >= NG - 2);
    const float mk0 = (ybord || x0     < 2 || x0     >= NG - 2) ? 0.0f : 1.0f;
    const float mk1 = (ybord || x0 + 1 < 2 || x0 + 1 >= NG - 2) ? 0.0f : 1.0f;
    const int ssc = (rr + 8) * SSP + (cx + 8);
    const int vvc = (rr + 6) * SVP + (cx + 6);

    unsigned smask = 0u;
#pragma unroll
    for (int s = 0; s < NSRC; s++) {
        int sy = sloc[(shot*NSRC + s)*2], sx = sloc[(shot*NSRC + s)*2 + 1];
        if (sy == y && sx == x0)     smask |= 1u << s;
        if (sy == y && sx == x0 + 1) smask |= 1u << (s + 8);
    }

    int rcode[8];
    int rcnt = 0;
    bool rovf = false;
    for (int r = 0; r < NREC; r++) {
        int e = shot * NREC + r;
        int ry = rloc[e*2], rx = rloc[e*2 + 1];
        if (ry == y && (rx == x0 || rx == x0 + 1)) {
            if (rcnt < 8) rcode[rcnt++] = e * 2 + (rx - x0);
            else rovf = true;
        }
    }

    // ---- ring slot descriptors ----
    const int v0rc = vring_rc(tid);                       // slot0: all 400 threads
    const int v1rc = (tid < 32) ? vring_rc(400 + tid) : 0;
    const int srrc = (tid < 272) ? sring_rc(tid) : 0;

    auto srcmask_at = [&](int rc) -> unsigned {
        int gy = gw(by0 + (rc >> 8) - 8), gx = gw(bx0 + (rc & 255) - 8);
        unsigned m = 0;
#pragma unroll
        for (int s = 0; s < NSRC; s++) {
            int sy = sloc[(shot*NSRC + s)*2], sx = sloc[(shot*NSRC + s)*2 + 1];
            if (sy == gy && sx == gx)     m |= 1u << s;
            if (sy == gy && sx == gx + 1) m |= 1u << (s + 8);
        }
        return m;
    };
    const unsigned v0mask = srcmask_at(v0rc);
    const unsigned v1mask = (tid < 32) ? srcmask_at(v1rc) : 0u;

    // ---- persistent core CPML (registers) ----
    float cms[8] = {0,0,0,0,0,0,0,0};   // [f + 4*cell]: msyyy,msxyx,msxxx,msxyy
    float cmv[8] = {0,0,0,0,0,0,0,0};   // mvyy,mvxx,mvyx,mvxy

    // ---- init: zero frames + buf0 core state ----
    for (int i = tid; i < 36*SSP; i += TPB) { s_syy[i] = 0.f; s_sxy[i] = 0.f; s_sxx[i] = 0.f; }
    for (int i = tid; i < 32*SVP; i += TPB) { s_vy[i] = 0.f; s_vx[i] = 0.f; }
    {
        int gq = base + o;
        st2(g_syy[0], gq, 0,0); st2(g_sxy[0], gq, 0,0); st2(g_sxx[0], gq, 0,0);
        st2(g_vyf[0], gq, 0,0); st2(g_vxf[0], gq, 0,0);
        st2(g_ms1[0], gq, 0,0); st2(g_ms2[0], gq, 0,0);
        st2(g_ms3[0], gq, 0,0); st2(g_ms4[0], gq, 0,0);
        st2(g_mv1[0], gq, 0,0); st2(g_mv2[0], gq, 0,0);
        st2(g_mv3[0], gq, 0,0); st2(g_mv4[0], gq, 0,0);
    }
    __syncthreads();
    if (tid == 0) { __threadfence(); red_add(&g_flag[blk * 32]); }   // flag = F+1

    const float C1 = 1.125f;
    const float C2 = -1.0f / 24.0f;

    auto vel_cell = [&](int ss, int vv, float byv_, float bxv_, float bv_, float mk_,
                        float src, float& m1, float& m2, float& m3, float& m4)
    {
        float d, m;
        d = (C1*(s_syy[ss] - s_syy[ss-SSP]) + C2*(s_syy[ss+SSP] - s_syy[ss-2*SSP])) * IDHF;
        m = m1; m = byv_*m + (byv_-1.0f)*d; m1 = m;
        float ay = d + m;
        d = (C1*(s_sxy[ss+1] - s_sxy[ss]) + C2*(s_sxy[ss+2] - s_sxy[ss-1])) * IDHF;
        m = m2; m = bxv_*m + (bxv_-1.0f)*d; m2 = m;
        ay += d + m;
        s_vy[vv] = (s_vy[vv] + DTF * bv_ * ay + src) * mk_;
        d = (C1*(s_sxx[ss] - s_sxx[ss-1]) + C2*(s_sxx[ss+1] - s_sxx[ss-2])) * IDHF;
        m = m3; m = bxv_*m + (bxv_-1.0f)*d; m3 = m;
        float ax = d + m;
        d = (C1*(s_sxy[ss+SSP] - s_sxy[ss]) + C2*(s_sxy[ss+2*SSP] - s_sxy[ss-SSP])) * IDHF;
        m = m4; m = byv_*m + (byv_-1.0f)*d; m4 = m;
        ax += d + m;
        s_vx[vv] = (s_vx[vv] + DTF * bv_ * ax) * mk_;
    };

    auto str_cell = [&](int ss, int vv, float byv_, float bxv_, float lam_, float mu_,
                        float mk_, float& m1, float& m2, float& m3, float& m4)
    {
        float l2m_ = lam_ + 2.0f * mu_;
        float d, m;
        d = (C1*(s_vy[vv+SVP] - s_vy[vv]) + C2*(s_vy[vv+2*SVP] - s_vy[vv-SVP])) * IDHF;
        m = m1; m = byv_*m + (byv_-1.0f)*d; m1 = m;
        float e1 = d + m;
        d = (C1*(s_vx[vv] - s_vx[vv-1]) + C2*(s_vx[vv+1] - s_vx[vv-2])) * IDHF;
        m = m2; m = bxv_*m + (bxv_-1.0f)*d; m2 = m;
        float e2 = d + m;
        float nsyy = (s_syy[ss] + DTF*(l2m_*e1 + lam_*e2)) * mk_;
        float nsxx = (s_sxx[ss] + DTF*(l2m_*e2 + lam_*e1)) * mk_;
        d = (C1*(s_vy[vv+1] - s_vy[vv]) + C2*(s_vy[vv+2] - s_vy[vv-1])) * IDHF;
        m = m3; m = bxv_*m + (bxv_-1.0f)*d; m3 = m;
        float g = d + m;
        d = (C1*(s_vx[vv] - s_vx[vv-SVP]) + C2*(s_vx[vv+SVP] - s_vx[vv-2*SVP])) * IDHF;
        m = m4; m = byv_*m + (byv_-1.0f)*d; m4 = m;
        g += d + m;
        float nsxy = (s_sxy[ss] + DTF * mu_ * g) * mk_;
        s_syy[ss] = nsyy; s_sxy[ss] = nsxy; s_sxx[ss] = nsxx;
    };

    auto vel_slot = [&](int rc, float* ms, unsigned mask, int tt)
    {
        int rF = rc >> 8, cF = rc & 255;
        int ss = rF * SSP + cF;
        int r = rF - 8, c = cF - 8;
        int vv = (r + 6) * SVP + (c + 6);
        int gy = gw(by0 + r), gx = gw(bx0 + c);
        float by_ = s_pml[gy], bxa = s_pml[gx], bxb = s_pml[gx + 1];
        int go = gy * NG + gx;
        float bva = buoy[go], bvb = buoy[go + 1];
        bool yb = (gy < 2 || gy >= NG - 2);
        float mka = (yb || gx < 2 || gx >= NG - 2) ? 0.f : 1.f;
        float mkb = (yb || gx + 1 >= NG - 2) ? 0.f : 1.f;
        float sa = 0.f, sb = 0.f;
        if (mask) {
#pragma unroll
            for (int s = 0; s < NSRC; s++) {
                float a = amps[(shot*NSRC + s)*NT + tt];
                if (mask & (1u << s))       sa += a;
                if (mask & (1u << (s + 8))) sb += a;
            }
            sa *= DTF * bva;
            sb *= DTF * bvb;
        }
        vel_cell(ss,     vv,     by_, bxa, bva, mka, sa, ms[0], ms[1], ms[2], ms[3]);
        vel_cell(ss + 1, vv + 1, by_, bxb, bvb, mkb, sb, ms[4], ms[5], ms[6], ms[7]);
    };

    auto str_slot = [&](int rc, float* mv)
    {
        int rF = rc >> 8, cF = rc & 255;
        int ss = rF * SSP + cF;
        int r = rF - 8, c = cF - 8;
        int vv = (r + 6) * SVP + (c + 6);
        int gy = gw(by0 + r), gx = gw(bx0 + c);
        float by_ = s_pml[gy], bxa = s_pml[gx], bxb = s_pml[gx + 1];
        int go = gy * NG + gx;
        float laa = lamb[go], lab = lamb[go + 1];
        float mua = mu[go],   mub = mu[go + 1];
        bool yb = (gy < 2 || gy >= NG - 2);
        float mka = (yb || gx < 2 || gx >= NG - 2) ? 0.f : 1.f;
        float mkb = (yb || gx + 1 >= NG - 2) ? 0.f : 1.f;
        str_cell(ss,     vv,     by_, bxa, laa, mua, mka, mv[0], mv[1], mv[2], mv[3]);
        str_cell(ss + 1, vv + 1, by_, bxb, lab, mub, mkb, mv[4], mv[5], mv[6], mv[7]);
    };

    const float byvC  = s_pml[y];
    const float bxv0C = s_pml[x0];
    const float bxv1C = s_pml[x0 + 1];

#pragma unroll 1
    for (int k = 0; k < NROUND; k++) {
        const int t2 = 2 * k;
        const int p = k & 1;
        const int q = p ^ 1;

        // [A] wait for 8 same-shot neighbors (round k-1 published)
        if (tid < 8) {
            const unsigned tgt = F + 1u + (unsigned)k;
            const unsigned* fp = &g_flag[nbid * 32];
            while ((int)(ld_acq(fp) - tgt) < 0) { }
        }
        __syncthreads();

        // [L] load annuli + ring CPML from buffer p
        float v0ms[8], v1ms[8], srmv[8];
        {
            const float* __restrict__ Syy = g_syy[p];
            const float* __restrict__ Sxy = g_sxy[p];
            const float* __restrict__ Sxx = g_sxx[p];
            for (int i = tid; i < 36*56; i += TPB) {
                int r = i / 56 - 8, c = i % 56 - 8;
                if (r >= 0 && r < TILE_R && c >= 0 && c < TILE_C) continue;
                int gi = base + gw(by0 + r) * NG + gw(bx0 + c);
                int si = (r + 8) * SSP + (c + 8);
                s_syy[si] = Syy[gi];
                s_sxy[si] = Sxy[gi];
                s_sxx[si] = Sxx[gi];
            }
            const float* __restrict__ Vy = g_vyf[p];
            const float* __restrict__ Vx = g_vxf[p];
            for (int i = tid; i < 32*52; i += TPB) {
                int r = i / 52 - 6, c = i % 52 - 6;
                if (r >= 0 && r < TILE_R && c >= 0 && c < TILE_C) continue;
                int gi = base + gw(by0 + r) * NG + gw(bx0 + c);
                int vi = (r + 6) * SVP + (c + 6);
                s_vy[vi] = Vy[gi];
                s_vx[vi] = Vx[gi];
            }
            // ring CPML loads
            {
                int gy = gw(by0 + (v0rc >> 8) - 8), gx = gw(bx0 + (v0rc & 255) - 8);
                int gp = base + gy * NG + gx;
                v0ms[0] = g_ms1[p][gp];   v0ms[1] = g_ms2[p][gp];
                v0ms[2] = g_ms3[p][gp];   v0ms[3] = g_ms4[p][gp];
                v0ms[4] = g_ms1[p][gp+1]; v0ms[5] = g_ms2[p][gp+1];
                v0ms[6] = g_ms3[p][gp+1]; v0ms[7] = g_ms4[p][gp+1];
            }
            if (tid < 32) {
                int gy = gw(by0 + (v1rc >> 8) - 8), gx = gw(bx0 + (v1rc & 255) - 8);
                int gp = base + gy * NG + gx;
                v1ms[0] = g_ms1[p][gp];   v1ms[1] = g_ms2[p][gp];
                v1ms[2] = g_ms3[p][gp];   v1ms[3] = g_ms4[p][gp];
                v1ms[4] = g_ms1[p][gp+1]; v1ms[5] = g_ms2[p][gp+1];
                v1ms[6] = g_ms3[p][gp+1]; v1ms[7] = g_ms4[p][gp+1];
            }
            if (tid < 272) {
                int gy = gw(by0 + (srrc >> 8) - 8), gx = gw(bx0 + (srrc & 255) - 8);
                int gp = base + gy * NG + gx;
                srmv[0] = g_mv1[p][gp];   srmv[1] = g_mv2[p][gp];
                srmv[2] = g_mv3[p][gp];   srmv[3] = g_mv4[p][gp];
                srmv[4] = g_mv1[p][gp+1]; srmv[5] = g_mv2[p][gp+1];
                srmv[6] = g_mv3[p][gp+1]; srmv[7] = g_mv4[p][gp+1];
            }
        }
        __syncthreads();

        // [V1] velocity step t on core+-6
        {
            float s0 = 0.f, s1 = 0.f;
            if (smask) {
#pragma unroll
                for (int s = 0; s < NSRC; s++) {
                    float a = amps[(shot*NSRC + s)*NT + t2];
                    if (smask & (1u << s))       s0 += a;
                    if (smask & (1u << (s + 8))) s1 += a;
                }
                s0 *= DTF * bv2.x;
                s1 *= DTF * bv2.y;
            }
            vel_cell(ssc,     vvc,     byvC, bxv0C, bv2.x, mk0, s0, cms[0], cms[1], cms[2], cms[3]);
            vel_cell(ssc + 1, vvc + 1, byvC, bxv1C, bv2.y, mk1, s1, cms[4], cms[5], cms[6], cms[7]);
            vel_slot(v0rc, v0ms, v0mask, t2);
            if (tid < 32) vel_slot(v1rc, v1ms, v1mask, t2);
        }
        __syncthreads();

        // receivers step t (s_vy stable during stress phase)
        if (rovf) {
            for (int r = 0; r < NREC; r++) {
                int e = shot * NREC + r;
                int ry = rloc[e*2], rx = rloc[e*2 + 1];
                if (ry == y && (rx == x0 || rx == x0 + 1))
                    g_recs[t2*(NSHOT*NREC) + e] = s_vy[vvc + (rx - x0)];
            }
        } else {
            for (int i = 0; i < rcnt; i++) {
                int e = rcode[i] >> 1, c = rcode[i] & 1;
                g_recs[t2*(NSHOT*NREC) + e] = s_vy[vvc + c];
            }
        }

        // [S1] stress step t on core+-4
        {
            str_cell(ssc,     vvc,     byvC, bxv0C, lam2.x, mu2.x, mk0, cmv[0], cmv[1], cmv[2], cmv[3]);
            str_cell(ssc + 1, vvc + 1, byvC, bxv1C, lam2.y, mu2.y, mk1, cmv[4], cmv[5], cmv[6], cmv[7]);
            if (tid < 272) str_slot(srrc, srmv);
        }
        __syncthreads();

        // [V2] velocity step t+1 on core+-2
        {
            float s0 = 0.f, s1 = 0.f;
            if (smask) {
#pragma unroll
                for (int s = 0; s < NSRC; s++) {
                    float a = amps[(shot*NSRC + s)*NT + t2 + 1];
                    if (smask & (1u << s))       s0 += a;
                    if (smask & (1u << (s + 8))) s1 += a;
                }
                s0 *= DTF * bv2.x;
                s1 *= DTF * bv2.y;
            }
            vel_cell(ssc,     vvc,     byvC, bxv0C, bv2.x, mk0, s0, cms[0], cms[1], cms[2], cms[3]);
            vel_cell(ssc + 1, vvc + 1, byvC, bxv1C, bv2.y, mk1, s1, cms[4], cms[5], cms[6], cms[7]);
            if (tid < 128) vel_slot(v0rc, v0ms, v0mask, t2 + 1);
        }
        __syncthreads();

        // receivers step t+1
        if (rovf) {
            for (int r = 0; r < NREC; r++) {
                int e = shot * NREC + r;
                int ry = rloc[e*2], rx = rloc[e*2 + 1];
                if (ry == y && (rx == x0 || rx == x0 + 1))
                    g_recs[(t2+1)*(NSHOT*NREC) + e] = s_vy[vvc + (rx - x0)];
            }
        } else {
            for (int i = 0; i < rcnt; i++) {
                int e = rcode[i] >> 1, c = rcode[i] & 1;
                g_recs[(t2+1)*(NSHOT*NREC) + e] = s_vy[vvc + c];
            }
        }

        // [S2] stress step t+1 on core only
        str_cell(ssc,     vvc,     byvC, bxv0C, lam2.x, mu2.x, mk0, cmv[0], cmv[1], cmv[2], cmv[3]);
        str_cell(ssc + 1, vvc + 1, byvC, bxv1C, lam2.y, mu2.y, mk1, cmv[4], cmv[5], cmv[6], cmv[7]);

        // [P] publish ALL core state (t+1) into buffer q
        {
            int gq = base + o;
            st2(g_syy[q], gq, s_syy[ssc], s_syy[ssc+1]);
            st2(g_sxy[q], gq, s_sxy[ssc], s_sxy[ssc+1]);
            st2(g_sxx[q], gq, s_sxx[ssc], s_sxx[ssc+1]);
            st2(g_vyf[q], gq, s_vy[vvc], s_vy[vvc+1]);
            st2(g_vxf[q], gq, s_vx[vvc], s_vx[vvc+1]);
            st2(g_ms1[q], gq, cms[0], cms[4]);
            st2(g_ms2[q], gq, cms[1], cms[5]);
            st2(g_ms3[q], gq, cms[2], cms[6]);
            st2(g_ms4[q], gq, cms[3], cms[7]);
            st2(g_mv1[q], gq, cmv[0], cmv[4]);
            st2(g_mv2[q], gq, cmv[1], cmv[5]);
            st2(g_mv3[q], gq, cmv[2], cmv[6]);
            st2(g_mv4[q], gq, cmv[3], cmv[7]);
        }
        __syncthreads();
        if (tid == 0) { __threadfence(); red_add(&g_flag[blk * 32]); }
    }

    // ---------------- finalize ----------------
    gbar(ph + 1);
    const int gtid = blk * TPB + tid;
    const int total = NSHOT * NREC * (NT - 1);
    if (gtid < total) {
        int t = gtid % (NT - 1);
        int e = gtid / (NT - 1);
        out[e * (NT - 1) + t] = 0.5f * (g_recs[(t + 1)*(NSHOT*NREC) + e]
                                      + g_recs[t      *(NSHOT*NREC) + e]);
    }
}

extern "C" void kernel_launch(void* const* d_in, const int* in_sizes, int n_in,
                              void* d_out, int out_size)
{
    const float* lamb = (const float*)d_in[0];
    const float* mu   = (const float*)d_in[1];
    const float* buoy = (const float*)d_in[2];
    const float* amps = (const float*)d_in[3];
    const int*   sloc = (const int*)d_in[4];
    const int*   rloc = (const int*)d_in[5];
    float* out = (float*)d_out;

    sim_kernel<<<NBLK, TPB>>>(lamb, mu, buoy, amps, sloc, rloc, out);
}